// round 5
// baseline (speedup 1.0000x reference)
#include <cuda_runtime.h>

#define NODES_MAX 50000
#define EDGES_MAX 800000
#define F 128

// Scratch (no runtime allocation allowed)
__device__ float g_P[NODES_MAX * F];       // h @ W1h^T + b1
__device__ float g_hN[NODES_MAX * F];      // mean-aggregated messages
__device__ float g_T[NODES_MAX * F];       // h @ W2a^T + b2
__device__ float g_W1T[F * F];             // [k][c] = W1[c*131 + k]
__device__ float g_W2aT[F * F];            // [k][c] = W2[c*256 + k]
__device__ float g_W2bT[F * F];            // [k][c] = W2[c*256 + 128 + k]
__device__ int   g_cnt[NODES_MAX];
__device__ int   g_off[NODES_MAX + 1];
__device__ int   g_cursor[NODES_MAX];
__device__ int4  g_recs[EDGES_MAX];        // {src, bits(w0), bits(w1), bits(w2)}

// ---------------------------------------------------------------------------
// Prep: transpose weights, zero degree counters
// ---------------------------------------------------------------------------
__global__ void prep_kernel(const float* __restrict__ W1,
                            const float* __restrict__ W2,
                            int n_nodes)
{
    int idx = blockIdx.x * blockDim.x + threadIdx.x;
    int stride = gridDim.x * blockDim.x;

    for (int i = idx; i < F * F; i += stride) {
        int c = i >> 7, k = i & 127;
        g_W1T[k * F + c]  = W1[c * 131 + k];
        g_W2aT[k * F + c] = W2[c * 256 + k];
        g_W2bT[k * F + c] = W2[c * 256 + 128 + k];
    }
    for (int i = idx; i < n_nodes; i += stride) g_cnt[i] = 0;
}

// ---------------------------------------------------------------------------
// CSR build: count -> scan (one block) -> scatter records
// ---------------------------------------------------------------------------
__global__ void count_kernel(const int* __restrict__ dst, int E)
{
    int e = blockIdx.x * blockDim.x + threadIdx.x;
    if (e < E) atomicAdd(&g_cnt[dst[e]], 1);
}

__global__ __launch_bounds__(1024) void scan_kernel(int M)
{
    __shared__ int s[1024];
    const int tid = threadIdx.x;
    const int per = (M + 1023) >> 10;
    const int base = tid * per;

    int local = 0;
    for (int i = 0; i < per; i++) {
        int idx = base + i;
        if (idx < M) local += g_cnt[idx];
    }
    s[tid] = local;
    __syncthreads();
    for (int off = 1; off < 1024; off <<= 1) {
        int v = 0;
        if (tid >= off) v = s[tid - off];
        __syncthreads();
        s[tid] += v;
        __syncthreads();
    }
    int run = s[tid] - local;      // exclusive prefix for this chunk
    for (int i = 0; i < per; i++) {
        int idx = base + i;
        if (idx < M) {
            g_off[idx]    = run;
            g_cursor[idx] = run;
            run += g_cnt[idx];
        }
    }
    if (tid == 1023) g_off[M] = s[1023];
}

__global__ void scatter_kernel(const int* __restrict__ src,
                               const int* __restrict__ dst,
                               const float* __restrict__ ew, int E)
{
    int e = blockIdx.x * blockDim.x + threadIdx.x;
    if (e >= E) return;
    int d = dst[e];
    int pos = atomicAdd(&g_cursor[d], 1);
    int4 r;
    r.x = src[e];
    r.y = __float_as_int(ew[e * 3 + 0]);
    r.z = __float_as_int(ew[e * 3 + 1]);
    r.w = __float_as_int(ew[e * 3 + 2]);
    g_recs[pos] = r;
}

// ---------------------------------------------------------------------------
// Core GEMM tile: FFMA2 inner loop + double-buffered smem (1 sync / K-step).
// C[row0+128][0:128] = A(Mx128) x Bt(128x128 [k][c]); epilogue bias or +T,relu.
// 256 threads, 8x8 micro-tile, BK=8.
// ---------------------------------------------------------------------------
template<bool ADD_T_RELU>
__device__ __forceinline__ void gemm_tile(
    const float* __restrict__ A, const float* __restrict__ Bt,
    const float* __restrict__ bias, const float* __restrict__ Tadd,
    float* __restrict__ out, int M, int row0)
{
    __shared__ float As[2][8][132];
    __shared__ float Bs[2][8][128];

    const int tid = threadIdx.x;
    const int tx = tid & 15;
    const int ty = tid >> 4;

    const int lm = tid >> 1;
    const int lk = (tid & 1) * 4;
    const int grow = row0 + lm;
    const bool arow_ok = (grow < M);

    const int bk = tid >> 5;
    const int bc = (tid & 31) * 4;

    unsigned long long acc[8][4];
    #pragma unroll
    for (int i = 0; i < 8; i++)
        #pragma unroll
        for (int j = 0; j < 4; j++) acc[i][j] = 0ull;

    auto loadA = [&](int k0) -> float4 {
        float4 v = make_float4(0.f, 0.f, 0.f, 0.f);
        if (arow_ok) v = *(const float4*)(A + grow * 128 + k0 + lk);
        return v;
    };
    auto storeS = [&](int b, float4 ra, float4 rb) {
        As[b][lk + 0][lm] = ra.x;
        As[b][lk + 1][lm] = ra.y;
        As[b][lk + 2][lm] = ra.z;
        As[b][lk + 3][lm] = ra.w;
        *(float4*)&Bs[b][bk][bc] = rb;
    };
    auto compute = [&](const float (*As_)[132], const float (*Bs_)[128]) {
        #pragma unroll
        for (int k = 0; k < 8; k++) {
            float a[8];
            *(float4*)&a[0] = *(const float4*)&As_[k][ty * 4];
            *(float4*)&a[4] = *(const float4*)&As_[k][64 + ty * 4];
            unsigned long long bp[4];
            double2 d0 = *(const double2*)&Bs_[k][tx * 4];
            double2 d1 = *(const double2*)&Bs_[k][64 + tx * 4];
            bp[0] = __double_as_longlong(d0.x);
            bp[1] = __double_as_longlong(d0.y);
            bp[2] = __double_as_longlong(d1.x);
            bp[3] = __double_as_longlong(d1.y);
            #pragma unroll
            for (int i = 0; i < 8; i++) {
                unsigned long long ad;
                asm("mov.b64 %0, {%1, %2};" : "=l"(ad) : "f"(a[i]), "f"(a[i]));
                #pragma unroll
                for (int j = 0; j < 4; j++)
                    asm("fma.rn.f32x2 %0, %1, %2, %0;"
                        : "+l"(acc[i][j]) : "l"(ad), "l"(bp[j]));
            }
        }
    };

    // prologue: fill buffer 0
    {
        float4 ra = loadA(0);
        float4 rb = *(const float4*)(Bt + bk * 128 + bc);
        storeS(0, ra, rb);
    }
    __syncthreads();

    #pragma unroll 1
    for (int k0 = 0; k0 < 128; k0 += 16) {
        // phase 0: compute buf0, prefetch+store buf1
        {
            float4 ra, rb;
            bool nxt = (k0 + 8) < 128;
            if (nxt) {
                ra = loadA(k0 + 8);
                rb = *(const float4*)(Bt + (k0 + 8 + bk) * 128 + bc);
            }
            compute(As[0], Bs[0]);
            if (nxt) {
                storeS(1, ra, rb);
                __syncthreads();
            }
        }
        // phase 1: compute buf1, prefetch+store buf0
        if ((k0 + 8) < 128) {
            float4 ra, rb;
            bool nxt = (k0 + 16) < 128;
            if (nxt) {
                ra = loadA(k0 + 16);
                rb = *(const float4*)(Bt + (k0 + 16 + bk) * 128 + bc);
            }
            compute(As[1], Bs[1]);
            if (nxt) {
                storeS(0, ra, rb);
                __syncthreads();
            }
        }
    }

    const int c0 = tx * 4;
    const int c1 = 64 + tx * 4;

    float4 bias0, bias1;
    if (!ADD_T_RELU) {
        bias0 = *(const float4*)(bias + c0);
        bias1 = *(const float4*)(bias + c1);
    }

    #pragma unroll
    for (int i = 0; i < 8; i++) {
        int gr = row0 + ((i < 4) ? (ty * 4 + i) : (64 + ty * 4 + i - 4));
        if (gr >= M) continue;
        float4 v0, v1;
        asm("mov.b64 {%0, %1}, %2;" : "=f"(v0.x), "=f"(v0.y) : "l"(acc[i][0]));
        asm("mov.b64 {%0, %1}, %2;" : "=f"(v0.z), "=f"(v0.w) : "l"(acc[i][1]));
        asm("mov.b64 {%0, %1}, %2;" : "=f"(v1.x), "=f"(v1.y) : "l"(acc[i][2]));
        asm("mov.b64 {%0, %1}, %2;" : "=f"(v1.z), "=f"(v1.w) : "l"(acc[i][3]));
        if (ADD_T_RELU) {
            float4 t0 = *(const float4*)(Tadd + gr * 128 + c0);
            float4 t1 = *(const float4*)(Tadd + gr * 128 + c1);
            v0.x = fmaxf(v0.x + t0.x, 0.f); v0.y = fmaxf(v0.y + t0.y, 0.f);
            v0.z = fmaxf(v0.z + t0.z, 0.f); v0.w = fmaxf(v0.w + t0.w, 0.f);
            v1.x = fmaxf(v1.x + t1.x, 0.f); v1.y = fmaxf(v1.y + t1.y, 0.f);
            v1.z = fmaxf(v1.z + t1.z, 0.f); v1.w = fmaxf(v1.w + t1.w, 0.f);
        } else {
            v0.x += bias0.x; v0.y += bias0.y; v0.z += bias0.z; v0.w += bias0.w;
            v1.x += bias1.x; v1.y += bias1.y; v1.z += bias1.z; v1.w += bias1.w;
        }
        *(float4*)(out + gr * 128 + c0) = v0;
        *(float4*)(out + gr * 128 + c1) = v1;
    }
}

// ---------------------------------------------------------------------------
// Dual GEMM: bid < nT -> g_P = h@W1h^T + b1 ; else -> g_T = h@W2a^T + b2
// ---------------------------------------------------------------------------
__global__ __launch_bounds__(256) void gemm_dual_kernel(
    const float* __restrict__ h, const float* __restrict__ b1,
    const float* __restrict__ b2, int M, int nT)
{
    int bid = blockIdx.x;
    if (bid < nT)
        gemm_tile<false>(h, g_W1T, b1, nullptr, g_P, M, bid * 128);
    else
        gemm_tile<false>(h, g_W2aT, b2, nullptr, g_T, M, (bid - nT) * 128);
}

// ---------------------------------------------------------------------------
// Aggregate: one warp per node; serial loop over its CSR edge segment,
// accumulate leaky(P[src] + w.C) in registers, write mean once.
// ---------------------------------------------------------------------------
__device__ __forceinline__ void edge_accum(
    float4& acc, float4 p, float w0, float w1, float w2,
    float4 cA, float4 cB, float4 cC)
{
    float t0 = p.x + w0 * cA.x + w1 * cB.x + w2 * cC.x;
    float t1 = p.y + w0 * cA.y + w1 * cB.y + w2 * cC.y;
    float t2 = p.z + w0 * cA.z + w1 * cB.z + w2 * cC.z;
    float t3 = p.w + w0 * cA.w + w1 * cB.w + w2 * cC.w;
    acc.x += (t0 < 0.f) ? 0.01f * t0 : t0;
    acc.y += (t1 < 0.f) ? 0.01f * t1 : t1;
    acc.z += (t2 < 0.f) ? 0.01f * t2 : t2;
    acc.w += (t3 < 0.f) ? 0.01f * t3 : t3;
}

__global__ __launch_bounds__(256) void aggregate_kernel(
    const float* __restrict__ W1, int M)
{
    __shared__ float cw[3][128];
    for (int i = threadIdx.x; i < 384; i += 256) {
        int t = i >> 7, j = i & 127;
        cw[t][j] = W1[j * 131 + 128 + t];
    }
    __syncthreads();

    const int warp = threadIdx.x >> 5;
    const int lane = threadIdx.x & 31;
    const int col  = lane * 4;
    const int node = blockIdx.x * 8 + warp;
    if (node >= M) return;

    const float4 cA = *(const float4*)&cw[0][col];
    const float4 cB = *(const float4*)&cw[1][col];
    const float4 cC = *(const float4*)&cw[2][col];

    const int beg = g_off[node];
    const int end = g_off[node + 1];

    float4 acc = make_float4(0.f, 0.f, 0.f, 0.f);
    int e = beg;
    for (; e + 2 <= end; e += 2) {
        int4 r0 = g_recs[e];
        int4 r1 = g_recs[e + 1];
        float4 p0 = *(const float4*)(g_P + (long)r0.x * 128 + col);
        float4 p1 = *(const float4*)(g_P + (long)r1.x * 128 + col);
        edge_accum(acc, p0, __int_as_float(r0.y), __int_as_float(r0.z),
                   __int_as_float(r0.w), cA, cB, cC);
        edge_accum(acc, p1, __int_as_float(r1.y), __int_as_float(r1.z),
                   __int_as_float(r1.w), cA, cB, cC);
    }
    if (e < end) {
        int4 r0 = g_recs[e];
        float4 p0 = *(const float4*)(g_P + (long)r0.x * 128 + col);
        edge_accum(acc, p0, __int_as_float(r0.y), __int_as_float(r0.z),
                   __int_as_float(r0.w), cA, cB, cC);
    }

    float inv = (end > beg) ? (1.0f / (float)(end - beg)) : 0.0f;
    float4 o = make_float4(acc.x * inv, acc.y * inv, acc.z * inv, acc.w * inv);
    *(float4*)(g_hN + (long)node * 128 + col) = o;
}

// ---------------------------------------------------------------------------
// GEMM3: out = relu( g_hN @ W2b^T + g_T )
// ---------------------------------------------------------------------------
__global__ __launch_bounds__(256) void gemm3_kernel(float* __restrict__ out, int M)
{
    gemm_tile<true>(g_hN, g_W2bT, nullptr, g_T, out, M, blockIdx.x * 128);
}

// ---------------------------------------------------------------------------
extern "C" void kernel_launch(void* const* d_in, const int* in_sizes, int n_in,
                              void* d_out, int out_size)
{
    const float* h    = (const float*)d_in[0];
    const int*   esrc = (const int*)  d_in[1];
    const int*   edst = (const int*)  d_in[2];
    const float* ew   = (const float*)d_in[3];
    const float* W1   = (const float*)d_in[4];
    const float* b1   = (const float*)d_in[5];
    const float* W2   = (const float*)d_in[6];
    const float* b2   = (const float*)d_in[7];
    float* out = (float*)d_out;

    int M = in_sizes[0] / 128;   // 50000 nodes
    int E = in_sizes[1];         // 800000 edges
    int nT = (M + 127) / 128;    // 391 gemm tiles

    prep_kernel<<<256, 256>>>(W1, W2, M);
    count_kernel<<<(E + 255) / 256, 256>>>(edst, E);
    scan_kernel<<<1, 1024>>>(M);
    gemm_dual_kernel<<<nT * 2, 256>>>(h, b1, b2, M, nT);
    scatter_kernel<<<(E + 255) / 256, 256>>>(esrc, edst, ew, E);
    aggregate_kernel<<<(M + 7) / 8, 256>>>(W1, M);
    gemm3_kernel<<<nT, 256>>>(out, M);
}

// round 6
// speedup vs baseline: 1.3107x; 1.3107x over previous
#include <cuda_runtime.h>

#define NODES_MAX 50000
#define F 128

// Scratch (no runtime allocation allowed)
__device__ float g_P[NODES_MAX * F];       // h @ W1h^T + b1
__device__ float g_sums[NODES_MAX * F];    // segment sums of leaky acts
__device__ float g_counts[NODES_MAX];      // in-degree
__device__ float g_W1T[F * F];             // [k][c] = W1[c*131 + k]
__device__ float g_W2T[256 * F];           // [k][c] = W2[c*256 + k], k<256

// ---------------------------------------------------------------------------
// Prep: transpose weights, zero accumulators
// ---------------------------------------------------------------------------
__global__ void prep_kernel(const float* __restrict__ W1,
                            const float* __restrict__ W2,
                            int n_nodes)
{
    int idx = blockIdx.x * blockDim.x + threadIdx.x;
    int stride = gridDim.x * blockDim.x;

    for (int i = idx; i < F * F; i += stride) {
        int c = i >> 7, k = i & 127;
        g_W1T[k * F + c] = W1[c * 131 + k];
    }
    for (int i = idx; i < 256 * F; i += stride) {
        int c = i & 127, k = i >> 7;
        g_W2T[k * F + c] = W2[c * 256 + k];
    }
    int nsum4 = (n_nodes * F) >> 2;
    float4* s4 = reinterpret_cast<float4*>(g_sums);
    float4 z = make_float4(0.f, 0.f, 0.f, 0.f);
    for (int i = idx; i < nsum4; i += stride) s4[i] = z;
    for (int i = idx; i < n_nodes; i += stride) g_counts[i] = 0.f;
}

// ---------------------------------------------------------------------------
// Core GEMM tile: FFMA2 inner loop, double-buffered smem, BK=8,
// 256 threads, 8x8 micro-tile. C[row0+128][0:128] = A x Bt([k][c]).
// KTOT = 128: A = A1 only.
// KTOT = 256: k<128 from A1, k>=128 from A2 scaled by 1/max(count,1).
// Epilogue: +bias, optional relu.
// ---------------------------------------------------------------------------
template<int KTOT, bool RELU>
__device__ __forceinline__ void gemm_tile(
    const float* __restrict__ A1, const float* __restrict__ A2,
    const float* __restrict__ Bt, const float* __restrict__ bias,
    float* __restrict__ out, int M, int row0)
{
    __shared__ float As[2][8][132];
    __shared__ float Bs[2][8][128];

    const int tid = threadIdx.x;
    const int tx = tid & 15;
    const int ty = tid >> 4;

    const int lm = tid >> 1;
    const int lk = (tid & 1) * 4;
    const int grow = row0 + lm;
    const bool arow_ok = (grow < M);

    const int bk = tid >> 5;
    const int bc = (tid & 31) * 4;

    float inv = 1.0f;
    if (KTOT == 256)
        inv = arow_ok ? (1.0f / fmaxf(g_counts[grow], 1.0f)) : 0.0f;

    unsigned long long acc[8][4];
    #pragma unroll
    for (int i = 0; i < 8; i++)
        #pragma unroll
        for (int j = 0; j < 4; j++) acc[i][j] = 0ull;

    auto loadA = [&](int k0) -> float4 {
        float4 v = make_float4(0.f, 0.f, 0.f, 0.f);
        if (arow_ok) {
            if (KTOT == 256 && k0 >= 128) {
                v = *(const float4*)(A2 + (long)grow * 128 + (k0 - 128) + lk);
                v.x *= inv; v.y *= inv; v.z *= inv; v.w *= inv;
            } else {
                v = *(const float4*)(A1 + (long)grow * 128 + k0 + lk);
            }
        }
        return v;
    };
    auto storeS = [&](int b, float4 ra, float4 rb) {
        As[b][lk + 0][lm] = ra.x;
        As[b][lk + 1][lm] = ra.y;
        As[b][lk + 2][lm] = ra.z;
        As[b][lk + 3][lm] = ra.w;
        *(float4*)&Bs[b][bk][bc] = rb;
    };
    auto compute = [&](const float (*As_)[132], const float (*Bs_)[128]) {
        #pragma unroll
        for (int k = 0; k < 8; k++) {
            float a[8];
            *(float4*)&a[0] = *(const float4*)&As_[k][ty * 4];
            *(float4*)&a[4] = *(const float4*)&As_[k][64 + ty * 4];
            unsigned long long bp[4];
            double2 d0 = *(const double2*)&Bs_[k][tx * 4];
            double2 d1 = *(const double2*)&Bs_[k][64 + tx * 4];
            bp[0] = __double_as_longlong(d0.x);
            bp[1] = __double_as_longlong(d0.y);
            bp[2] = __double_as_longlong(d1.x);
            bp[3] = __double_as_longlong(d1.y);
            #pragma unroll
            for (int i = 0; i < 8; i++) {
                unsigned long long ad;
                asm("mov.b64 %0, {%1, %2};" : "=l"(ad) : "f"(a[i]), "f"(a[i]));
                #pragma unroll
                for (int j = 0; j < 4; j++)
                    asm("fma.rn.f32x2 %0, %1, %2, %0;"
                        : "+l"(acc[i][j]) : "l"(ad), "l"(bp[j]));
            }
        }
    };

    // prologue: fill buffer 0
    {
        float4 ra = loadA(0);
        float4 rb = *(const float4*)(Bt + bk * 128 + bc);
        storeS(0, ra, rb);
    }
    __syncthreads();

    #pragma unroll 1
    for (int k0 = 0; k0 < KTOT; k0 += 16) {
        {
            float4 ra, rb;
            bool nxt = (k0 + 8) < KTOT;
            if (nxt) {
                ra = loadA(k0 + 8);
                rb = *(const float4*)(Bt + (k0 + 8 + bk) * 128 + bc);
            }
            compute(As[0], Bs[0]);
            if (nxt) {
                storeS(1, ra, rb);
                __syncthreads();
            }
        }
        if ((k0 + 8) < KTOT) {
            float4 ra, rb;
            bool nxt = (k0 + 16) < KTOT;
            if (nxt) {
                ra = loadA(k0 + 16);
                rb = *(const float4*)(Bt + (k0 + 16 + bk) * 128 + bc);
            }
            compute(As[1], Bs[1]);
            if (nxt) {
                storeS(0, ra, rb);
                __syncthreads();
            }
        }
    }

    const int c0 = tx * 4;
    const int c1 = 64 + tx * 4;
    float4 bias0 = *(const float4*)(bias + c0);
    float4 bias1 = *(const float4*)(bias + c1);

    #pragma unroll
    for (int i = 0; i < 8; i++) {
        int gr = row0 + ((i < 4) ? (ty * 4 + i) : (64 + ty * 4 + i - 4));
        if (gr >= M) continue;
        float4 v0, v1;
        asm("mov.b64 {%0, %1}, %2;" : "=f"(v0.x), "=f"(v0.y) : "l"(acc[i][0]));
        asm("mov.b64 {%0, %1}, %2;" : "=f"(v0.z), "=f"(v0.w) : "l"(acc[i][1]));
        asm("mov.b64 {%0, %1}, %2;" : "=f"(v1.x), "=f"(v1.y) : "l"(acc[i][2]));
        asm("mov.b64 {%0, %1}, %2;" : "=f"(v1.z), "=f"(v1.w) : "l"(acc[i][3]));
        v0.x += bias0.x; v0.y += bias0.y; v0.z += bias0.z; v0.w += bias0.w;
        v1.x += bias1.x; v1.y += bias1.y; v1.z += bias1.z; v1.w += bias1.w;
        if (RELU) {
            v0.x = fmaxf(v0.x, 0.f); v0.y = fmaxf(v0.y, 0.f);
            v0.z = fmaxf(v0.z, 0.f); v0.w = fmaxf(v0.w, 0.f);
            v1.x = fmaxf(v1.x, 0.f); v1.y = fmaxf(v1.y, 0.f);
            v1.z = fmaxf(v1.z, 0.f); v1.w = fmaxf(v1.w, 0.f);
        }
        *(float4*)(out + (long)gr * 128 + c0) = v0;
        *(float4*)(out + (long)gr * 128 + c1) = v1;
    }
}

// ---------------------------------------------------------------------------
// GEMM1: g_P = h @ W1h^T + b1
// ---------------------------------------------------------------------------
__global__ __launch_bounds__(256) void gemm1_kernel(
    const float* __restrict__ h, const float* __restrict__ b1, int M)
{
    gemm_tile<128, false>(h, nullptr, g_W1T, b1, g_P, M, blockIdx.x * 128);
}

// ---------------------------------------------------------------------------
// Edge kernel (r4, proven): one warp per edge, x4 unrolled grid-stride,
// red.global.add.v4.f32 scatter into g_sums, count bump by lane 0.
// ---------------------------------------------------------------------------
__global__ __launch_bounds__(256) void edge_kernel(
    const int* __restrict__ src, const int* __restrict__ dst,
    const float* __restrict__ ew, const float* __restrict__ W1, int E)
{
    __shared__ float cw[3][128];
    for (int i = threadIdx.x; i < 384; i += 256) {
        int t = i >> 7, j = i & 127;
        cw[t][j] = W1[j * 131 + 128 + t];
    }
    __syncthreads();

    const int lane = threadIdx.x & 31;
    const int col  = lane * 4;
    const float4 cA = *(const float4*)&cw[0][col];
    const float4 cB = *(const float4*)&cw[1][col];
    const float4 cC = *(const float4*)&cw[2][col];

    const int gwarp  = (blockIdx.x * 256 + threadIdx.x) >> 5;
    const int nwarps = (gridDim.x * 256) >> 5;

    for (int e0 = gwarp; e0 < E; e0 += nwarps * 4) {
        int   se[4], de[4];
        float w0[4], w1[4], w2[4];
        float4 p[4];
        bool  v[4];

        #pragma unroll
        for (int u = 0; u < 4; u++) {
            int e = e0 + u * nwarps;
            v[u] = (e < E);
            if (v[u]) {
                se[u] = src[e];
                de[u] = dst[e];
                w0[u] = ew[e * 3 + 0];
                w1[u] = ew[e * 3 + 1];
                w2[u] = ew[e * 3 + 2];
            }
        }
        #pragma unroll
        for (int u = 0; u < 4; u++)
            if (v[u]) p[u] = *(const float4*)(g_P + (long)se[u] * 128 + col);

        #pragma unroll
        for (int u = 0; u < 4; u++) {
            if (!v[u]) continue;
            float t0 = p[u].x + w0[u] * cA.x + w1[u] * cB.x + w2[u] * cC.x;
            float t1 = p[u].y + w0[u] * cA.y + w1[u] * cB.y + w2[u] * cC.y;
            float t2 = p[u].z + w0[u] * cA.z + w1[u] * cB.z + w2[u] * cC.z;
            float t3 = p[u].w + w0[u] * cA.w + w1[u] * cB.w + w2[u] * cC.w;
            t0 = (t0 < 0.f) ? 0.01f * t0 : t0;
            t1 = (t1 < 0.f) ? 0.01f * t1 : t1;
            t2 = (t2 < 0.f) ? 0.01f * t2 : t2;
            t3 = (t3 < 0.f) ? 0.01f * t3 : t3;
            float* addr = g_sums + (long)de[u] * 128 + col;
            asm volatile("red.global.add.v4.f32 [%0], {%1, %2, %3, %4};"
                         :: "l"(addr), "f"(t0), "f"(t1), "f"(t2), "f"(t3)
                         : "memory");
            if (lane == 0) atomicAdd(&g_counts[de[u]], 1.0f);
        }
    }
}

// ---------------------------------------------------------------------------
// GEMM2 (K=256): out = relu( [h | g_sums*inv_count] @ W2^T + b2 )
// ---------------------------------------------------------------------------
__global__ __launch_bounds__(256) void gemm2_kernel(
    const float* __restrict__ h, const float* __restrict__ b2,
    float* __restrict__ out, int M)
{
    gemm_tile<256, true>(h, g_sums, g_W2T, b2, out, M, blockIdx.x * 128);
}

// ---------------------------------------------------------------------------
extern "C" void kernel_launch(void* const* d_in, const int* in_sizes, int n_in,
                              void* d_out, int out_size)
{
    const float* h    = (const float*)d_in[0];
    const int*   esrc = (const int*)  d_in[1];
    const int*   edst = (const int*)  d_in[2];
    const float* ew   = (const float*)d_in[3];
    const float* W1   = (const float*)d_in[4];
    const float* b1   = (const float*)d_in[5];
    const float* W2   = (const float*)d_in[6];
    const float* b2   = (const float*)d_in[7];
    float* out = (float*)d_out;

    int M = in_sizes[0] / 128;   // 50000 nodes
    int E = in_sizes[1];         // 800000 edges
    int nT = (M + 127) / 128;    // 391 gemm tiles

    prep_kernel<<<512, 256>>>(W1, W2, M);
    gemm1_kernel<<<nT, 256>>>(h, b1, M);
    edge_kernel<<<1480, 256>>>(esrc, edst, ew, W1, E);
    gemm2_kernel<<<nT, 256>>>(h, b2, out, M);
}